// round 4
// baseline (speedup 1.0000x reference)
#include <cuda_runtime.h>
#include <cuda_bf16.h>

#define BN 64
#define SEQ 48
#define HD 256
#define MM 193
#define TSTEPS 96

// ------------- device scratch -------------
__device__ float g_B [BN*SEQ*HD];
__device__ float g_sb[BN*SEQ];
__device__ float g_V [BN*MM*HD];
__device__ float g_s [BN*MM];
__device__ float g_c [BN*HD];
__device__ float g_At [1024*BN];   // k-major activations [xb|x1|x2|h]
__device__ float g_A2t[512*BN];    // k-major [r1|r2]
__device__ float g_Wf[1024*1024];  // [k][j] fused wih|whh
__device__ float g_bf[1024];
__device__ float g_Wt[512*1280];   // [k][j] fused lw|rw
__device__ float g_bt[1280];
__device__ float g_Wm0[256*1024];
__device__ float g_Wm1[1024*1024];
__device__ float g_Gp[8*BN*1024];
__device__ float g_Tp[4*BN*1280];
__device__ float g_y0[BN*1024];
__device__ float g_y1[BN*1024];
__device__ int   g_is64;

__device__ __forceinline__ float sigf(float x){ return 1.f/(1.f+expf(-x)); }

// ------------- warp scans -------------
__device__ __forceinline__ void scan_stack(float* srow, float a, float* w1, float* wt, bool pop){
  int lane = threadIdx.x & 31;
  float run = 0.f;
  #pragma unroll
  for (int c = 0; c < 7; c++){
    int m = c*32 + lane;
    float sv = (m < MM) ? srow[m] : 0.f;
    float v = sv;
    #pragma unroll
    for (int o = 1; o < 32; o <<= 1){
      float n = __shfl_up_sync(0xffffffffu, v, o);
      if (lane >= o) v += n;
    }
    float Pm = run + v, Pp = Pm - sv;
    float u1 = fminf(Pm, a) - fminf(Pp, a);
    float ut = fminf(Pm, 1.f + a) - fminf(Pp, 1.f + a);
    if (m < MM){ w1[m] = u1; wt[m] = ut; if (pop) srow[m] = sv - ut; }
    run += __shfl_sync(0xffffffffu, v, 31);
  }
  __syncwarp();
}

__device__ __forceinline__ void scan_buf(float* srow, float a, float* wb, bool pop){
  int lane = threadIdx.x & 31;
  float run = 0.f;
  #pragma unroll
  for (int c = 0; c < 2; c++){
    int m = c*32 + lane;
    float sv = (m < SEQ) ? srow[m] : 0.f;
    float v = sv;
    #pragma unroll
    for (int o = 1; o < 32; o <<= 1){
      float n = __shfl_up_sync(0xffffffffu, v, o);
      if (lane >= o) v += n;
    }
    float Pm = run + v, Pp = Pm - sv;
    float w = fminf(Pm, a) - fminf(Pp, a);
    if (m < SEQ){ wb[m] = w; if (pop) srow[m] = sv - w; }
    run += __shfl_sync(0xffffffffu, v, 31);
  }
  __syncwarp();
}

// ------------- token dtype detect -------------
__global__ void k_tok(const void* x){
  __shared__ int ok;
  if (threadIdx.x == 0) ok = 1;
  __syncthreads();
  const long long* xl = (const long long*)x;
  int bad = 0;
  for (int i = threadIdx.x; i < (BN*SEQ)/2; i += 256){
    long long v = xl[i];
    if (v < 0 || v >= 50257) bad = 1;
  }
  if (bad) atomicAnd(&ok, 0);
  __syncthreads();
  if (threadIdx.x == 0) g_is64 = ok;
}

// ------------- prep: transpose weights, gather emb, init state -------------
__global__ void k_prep(const void* x, const float* emb,
                       const float* wih, const float* whh,
                       const float* bih, const float* bhh,
                       const float* lw, const float* lb,
                       const float* rw, const float* rb,
                       const float* l0w, const float* l1w){
  int gid = blockIdx.x*blockDim.x + threadIdx.x;
  int gsz = gridDim.x*blockDim.x;
  int is64 = g_is64;
  const long long* xl = (const long long*)x;
  const int* xi = (const int*)x;
  for (int i = gid; i < BN*SEQ; i += gsz){
    long long tok = is64 ? xl[i] : (long long)xi[i];
    g_sb[i] = (tok > 0) ? 1.f : 0.f;
  }
  for (int i = gid; i < BN*SEQ*HD; i += gsz){
    int row = i >> 8;
    long long tok = is64 ? xl[row] : (long long)xi[row];
    g_B[i] = emb[(size_t)tok*HD + (i & 255)];
  }
  for (int i = gid; i < 1024*1024; i += gsz){
    int k = i >> 10, j = i & 1023;
    g_Wf[i] = (k < 768) ? wih[j*768 + k] : whh[j*256 + (k-768)];
  }
  for (int i = gid; i < 512*1280; i += gsz){
    int k = i/1280, j = i%1280;
    g_Wt[i] = (k < 256) ? lw[j*256 + k] : rw[j*256 + (k-256)];
  }
  for (int i = gid; i < 1024; i += gsz) g_bf[i] = bih[i] + bhh[i];
  for (int i = gid; i < 1280; i += gsz) g_bt[i] = lb[i] + rb[i];
  for (int i = gid; i < 256*1024; i += gsz){ int k = i >> 10, j = i & 1023; g_Wm0[i] = l0w[j*256 + k]; }
  for (int i = gid; i < 1024*1024; i += gsz){ int k = i >> 10, j = i & 1023; g_Wm1[i] = l1w[j*1024 + k]; }
  for (int i = gid; i < BN*MM*HD; i += gsz) g_V[i] = 0.f;
  for (int i = gid; i < BN*MM; i += gsz) g_s[i] = 0.f;
  for (int i = gid; i < 1024*BN; i += gsz) g_At[i] = 0.f;
  for (int i = gid; i < BN*HD; i += gsz) g_c[i] = 0.f;
}

// ------------- tiled GEMM with k-split partials -------------
// P[ks][b][j] += At[k][b] * W[k][j] over the block's 128-k slice, 64x64 tile
__device__ __forceinline__ void gemm_body(const float* __restrict__ At,
                                          const float* __restrict__ W,
                                          float* __restrict__ P, int J, int nks){
  int jt = blockIdx.x / nks, ks = blockIdx.x % nks;
  int j0 = jt*64, k0 = ks*128;
  __shared__ float sA[8][68];
  __shared__ float sW[8][64];
  int tx = threadIdx.x & 15, ty = threadIdx.x >> 4;
  float acc[4][4] = {};
  for (int kc = 0; kc < 16; kc++){
    int kb = k0 + kc*8;
    #pragma unroll
    for (int i = threadIdx.x; i < 512; i += 256){
      int kk = i >> 6, r = i & 63;
      sA[kk][r] = At[(kb+kk)*64 + r];
      sW[kk][r] = W[(kb+kk)*J + j0 + r];
    }
    __syncthreads();
    #pragma unroll
    for (int kk = 0; kk < 8; kk++){
      float4 a = *(const float4*)&sA[kk][4*ty];
      float4 w = *(const float4*)&sW[kk][4*tx];
      acc[0][0]=fmaf(a.x,w.x,acc[0][0]); acc[0][1]=fmaf(a.x,w.y,acc[0][1]); acc[0][2]=fmaf(a.x,w.z,acc[0][2]); acc[0][3]=fmaf(a.x,w.w,acc[0][3]);
      acc[1][0]=fmaf(a.y,w.x,acc[1][0]); acc[1][1]=fmaf(a.y,w.y,acc[1][1]); acc[1][2]=fmaf(a.y,w.z,acc[1][2]); acc[1][3]=fmaf(a.y,w.w,acc[1][3]);
      acc[2][0]=fmaf(a.z,w.x,acc[2][0]); acc[2][1]=fmaf(a.z,w.y,acc[2][1]); acc[2][2]=fmaf(a.z,w.z,acc[2][2]); acc[2][3]=fmaf(a.z,w.w,acc[2][3]);
      acc[3][0]=fmaf(a.w,w.x,acc[3][0]); acc[3][1]=fmaf(a.w,w.y,acc[3][1]); acc[3][2]=fmaf(a.w,w.z,acc[3][2]); acc[3][3]=fmaf(a.w,w.w,acc[3][3]);
    }
    __syncthreads();
  }
  #pragma unroll
  for (int i = 0; i < 4; i++){
    float4 v = make_float4(acc[i][0], acc[i][1], acc[i][2], acc[i][3]);
    *(float4*)&P[(ks*64 + 4*ty + i)*J + j0 + 4*tx] = v;
  }
}

__global__ void __launch_bounds__(256) k_lstm(){ gemm_body(g_At,  g_Wf, g_Gp, 1024, 8); }
__global__ void __launch_bounds__(256) k_tree(){ gemm_body(g_A2t, g_Wt, g_Tp, 1280, 4); }

// ------------- pointwise: gates, alphas, popping reads -------------
__global__ void __launch_bounds__(256) k_point(int t, const float* __restrict__ aw,
                                               const float* __restrict__ ab){
  int b = blockIdx.x, tid = threadIdx.x, warp = tid >> 5, lane = tid & 31;
  __shared__ float sg[1024], sh[256], w1[224], wt[224], wb[64], red[16];
  __shared__ float s_ar;
  for (int j = tid; j < 1024; j += 256){
    float v = g_bf[j];
    #pragma unroll
    for (int ks = 0; ks < 8; ks++) v += g_Gp[(ks*64 + b)*1024 + j];
    sg[j] = v;
  }
  __syncthreads();
  {
    int h = tid;
    float gi = sg[h], gf = sg[256+h], gg = sg[512+h], go = sg[768+h];
    float c = g_c[b*HD + h];
    c = sigf(gf)*c + sigf(gi)*tanhf(gg);
    float hh = sigf(go)*tanhf(c);
    g_c[b*HD + h] = c;
    sh[h] = hh;
    g_At[(768+h)*64 + b] = hh;
    float p0 = hh*aw[h], p1 = hh*aw[256+h];
    #pragma unroll
    for (int o = 16; o >= 1; o >>= 1){
      p0 += __shfl_xor_sync(0xffffffffu, p0, o);
      p1 += __shfl_xor_sync(0xffffffffu, p1, o);
    }
    if (lane == 0){ red[warp] = p0; red[8+warp] = p1; }
  }
  __syncthreads();
  if (tid == 0){
    float d0 = ab[0], d1 = ab[1];
    for (int w = 0; w < 8; w++){ d0 += red[w]; d1 += red[8+w]; }
    s_ar = sigf(10.f*(d0 - d1));
  }
  __syncthreads();
  float ar = s_ar, as = 1.f - ar;
  int idx = 191 - 2*t, idx2 = 190 - 2*t;
  if (warp == 0){
    scan_stack(&g_s[b*MM], ar, w1, wt, true);
    if (lane == 0){ g_s[b*MM + idx] = ar; g_s[b*MM + idx2] = as; }
  } else if (warp == 1){
    scan_buf(&g_sb[b*SEQ], as, wb, true);
  }
  __syncthreads();
  {
    int h = tid;
    float r1 = 0.f, r2 = 0.f;
    const float* Vb = g_V + (b*MM)*HD + h;
    for (int m = 0; m < MM; m++){
      float tw = wt[m];
      if (tw != 0.f){
        float v = Vb[m*HD];
        r1 = fmaf(w1[m], v, r1);
        r2 = fmaf(tw - w1[m], v, r2);
      }
    }
    g_A2t[h*64 + b] = r1;
    g_A2t[(256+h)*64 + b] = r2;
    float bv = 0.f;
    const float* Bb = g_B + (b*SEQ)*HD + h;
    for (int s2 = 0; s2 < SEQ; s2++){
      float w = wb[s2];
      if (w != 0.f) bv = fmaf(w, Bb[s2*HD], bv);
    }
    g_V[(b*MM + idx2)*HD + h] = bv;
  }
}

// ------------- epilogue: tree cell + next-step alpha=1 reads -------------
__global__ void __launch_bounds__(256) k_epi(int t){
  int b = blockIdx.x, tid = threadIdx.x, warp = tid >> 5;
  __shared__ float stg[1280], w1[224], wt[224], wb[64];
  if (t >= 0){
    for (int j = tid; j < 1280; j += 256){
      float v = g_bt[j];
      #pragma unroll
      for (int ks = 0; ks < 4; ks++) v += g_Tp[(ks*64 + b)*1280 + j];
      stg[j] = v;
    }
    __syncthreads();
    int h = tid;
    float ta = stg[h], ti = stg[256+h], f1 = stg[512+h], f2 = stg[768+h], to = stg[1024+h];
    float r1 = g_A2t[h*64 + b], r2 = g_A2t[(256+h)*64 + b];
    float ct = tanhf(ta)*sigf(ti) + sigf(f1)*r1 + sigf(f2)*r2;
    float ht = sigf(to)*tanhf(ct);
    g_V[(b*MM + (191 - 2*t))*HD + h] = ht;
    __syncthreads();
  }
  if (warp == 0) scan_stack(&g_s[b*MM], 1.f, w1, wt, false);
  else if (warp == 1) scan_buf(&g_sb[b*SEQ], 1.f, wb, false);
  __syncthreads();
  int h = tid;
  float xb = 0.f;
  const float* Bb = g_B + (b*SEQ)*HD + h;
  for (int s2 = 0; s2 < SEQ; s2++){
    float w = wb[s2];
    if (w != 0.f) xb = fmaf(w, Bb[s2*HD], xb);
  }
  float x1 = 0.f, x2 = 0.f;
  const float* Vb = g_V + (b*MM)*HD + h;
  for (int m = 0; m < MM; m++){
    float tw = wt[m];
    if (tw != 0.f){
      float v = Vb[m*HD];
      x1 = fmaf(w1[m], v, x1);
      x2 = fmaf(tw - w1[m], v, x2);
    }
  }
  g_At[h*64 + b] = xb;
  g_At[(256+h)*64 + b] = x1;
  g_At[(512+h)*64 + b] = x2;
}

// ------------- MLP head -------------
__global__ void __launch_bounds__(256) k_mlp0(const float* __restrict__ l0b){
  int b = blockIdx.x, tid = threadIdx.x;
  __shared__ float xs[256];
  xs[tid] = g_At[(256+tid)*64 + b];
  __syncthreads();
  float4 acc = *(const float4*)&l0b[4*tid];
  for (int k = 0; k < 256; k++){
    float4 w = *(const float4*)&g_Wm0[k*1024 + 4*tid];
    float x = xs[k];
    acc.x = fmaf(x, w.x, acc.x); acc.y = fmaf(x, w.y, acc.y);
    acc.z = fmaf(x, w.z, acc.z); acc.w = fmaf(x, w.w, acc.w);
  }
  acc.x = fmaxf(acc.x, 0.f); acc.y = fmaxf(acc.y, 0.f);
  acc.z = fmaxf(acc.z, 0.f); acc.w = fmaxf(acc.w, 0.f);
  *(float4*)&g_y0[b*1024 + 4*tid] = acc;
}

__global__ void __launch_bounds__(256) k_mlp1(const float* __restrict__ l1b){
  int b = blockIdx.x, tid = threadIdx.x;
  __shared__ float xs[1024];
  for (int i = tid; i < 1024; i += 256) xs[i] = g_y0[b*1024 + i];
  __syncthreads();
  float4 acc = *(const float4*)&l1b[4*tid];
  for (int k = 0; k < 1024; k++){
    float4 w = *(const float4*)&g_Wm1[k*1024 + 4*tid];
    float x = xs[k];
    acc.x = fmaf(x, w.x, acc.x); acc.y = fmaf(x, w.y, acc.y);
    acc.z = fmaf(x, w.z, acc.z); acc.w = fmaf(x, w.w, acc.w);
  }
  acc.x = fmaxf(acc.x, 0.f); acc.y = fmaxf(acc.y, 0.f);
  acc.z = fmaxf(acc.z, 0.f); acc.w = fmaxf(acc.w, 0.f);
  *(float4*)&g_y1[b*1024 + 4*tid] = acc;
}

__global__ void __launch_bounds__(256) k_mlp2(const float* __restrict__ l2w,
                                              const float* __restrict__ l2b,
                                              float* __restrict__ out){
  int b = blockIdx.x, tid = threadIdx.x, warp = tid >> 5, lane = tid & 31;
  __shared__ float red[8];
  for (int c = 0; c < 3; c++){
    float p = 0.f;
    for (int k = tid; k < 1024; k += 256)
      p = fmaf(g_y1[b*1024 + k], l2w[c*1024 + k], p);
    #pragma unroll
    for (int o = 16; o >= 1; o >>= 1) p += __shfl_xor_sync(0xffffffffu, p, o);
    if (lane == 0) red[warp] = p;
    __syncthreads();
    if (tid == 0){
      float s = l2b[c];
      for (int w = 0; w < 8; w++) s += red[w];
      out[b*3 + c] = s;
    }
    __syncthreads();
  }
}

// ------------- launch -------------
extern "C" void kernel_launch(void* const* d_in, const int* in_sizes, int n_in,
                              void* d_out, int out_size){
  const void*  x   = d_in[0];
  const float* emb = (const float*)d_in[1];
  const float* wih = (const float*)d_in[2];
  const float* whh = (const float*)d_in[3];
  const float* bih = (const float*)d_in[4];
  const float* bhh = (const float*)d_in[5];
  const float* aw  = (const float*)d_in[6];
  const float* ab  = (const float*)d_in[7];
  const float* lw  = (const float*)d_in[8];
  const float* lb  = (const float*)d_in[9];
  const float* rw  = (const float*)d_in[10];
  const float* rb  = (const float*)d_in[11];
  const float* l0w = (const float*)d_in[12];
  const float* l0b = (const float*)d_in[13];
  const float* l1w = (const float*)d_in[14];
  const float* l1b = (const float*)d_in[15];
  const float* l2w = (const float*)d_in[16];
  const float* l2b = (const float*)d_in[17];
  float* out = (float*)d_out;

  k_tok<<<1, 256>>>(x);
  k_prep<<<512, 256>>>(x, emb, wih, whh, bih, bhh, lw, lb, rw, rb, l0w, l1w);
  k_epi<<<64, 256>>>(-1);
  for (int t = 0; t < TSTEPS; t++){
    k_lstm<<<128, 256>>>();
    k_point<<<64, 256>>>(t, aw, ab);
    k_tree<<<80, 256>>>();
    k_epi<<<64, 256>>>(t);
  }
  k_mlp0<<<64, 256>>>(l0b);
  k_mlp1<<<64, 256>>>(l1b);
  k_mlp2<<<64, 256>>>(l2w, l2b, out);
}

// round 5
// speedup vs baseline: 1.4717x; 1.4717x over previous
#include <cuda_runtime.h>
#include <cuda_bf16.h>

#define BN 64
#define SEQ 48
#define HD 256
#define MM 193
#define TSTEPS 96

// ------------- device scratch -------------
__device__ float g_B [BN*SEQ*HD];
__device__ float g_sb[BN*SEQ];
__device__ float g_V [BN*MM*HD];
__device__ float g_s [BN*MM];
__device__ float g_c [BN*HD];
__device__ float g_At [1024*BN];   // k-major activations [xb|x1|x2|h]
__device__ float g_A2t[512*BN];    // k-major [r1|r2]
__device__ float g_Wf[1024*1024];  // [k][j] fused wih|whh
__device__ float g_bf[1024];
__device__ float g_Wt[512*1280];   // [k][j] fused lw|rw
__device__ float g_bt[1280];
__device__ float g_Wm0[256*1024];
__device__ float g_Wm1[1024*1024];
__device__ float g_Gp[16*BN*1024];
__device__ float g_Tp[8*BN*1280];
__device__ float g_y0[BN*1024];
__device__ float g_y1[BN*1024];
__device__ int   g_is64;

__device__ __forceinline__ float sigf(float x){ return 1.f/(1.f+expf(-x)); }

#define FMA2(d,a,b) asm("fma.rn.f32x2 %0, %1, %2, %0;" : "+l"(d) : "l"(a), "l"(b))
__device__ __forceinline__ unsigned long long splat2(float x){
  unsigned long long r; asm("mov.b64 %0, {%1, %1};" : "=l"(r) : "f"(x)); return r;
}

// ------------- warp scans -------------
__device__ __forceinline__ void scan_stack(float* srow, float a, float* w1, float* wt, bool pop){
  int lane = threadIdx.x & 31;
  float run = 0.f;
  #pragma unroll
  for (int c = 0; c < 7; c++){
    int m = c*32 + lane;
    float sv = (m < MM) ? srow[m] : 0.f;
    float v = sv;
    #pragma unroll
    for (int o = 1; o < 32; o <<= 1){
      float n = __shfl_up_sync(0xffffffffu, v, o);
      if (lane >= o) v += n;
    }
    float Pm = run + v, Pp = Pm - sv;
    float u1 = fminf(Pm, a) - fminf(Pp, a);
    float ut = fminf(Pm, 1.f + a) - fminf(Pp, 1.f + a);
    if (m < MM){ w1[m] = u1; wt[m] = ut; if (pop) srow[m] = sv - ut; }
    run += __shfl_sync(0xffffffffu, v, 31);
  }
  __syncwarp();
}

__device__ __forceinline__ void scan_buf(float* srow, float a, float* wb, bool pop){
  int lane = threadIdx.x & 31;
  float run = 0.f;
  #pragma unroll
  for (int c = 0; c < 2; c++){
    int m = c*32 + lane;
    float sv = (m < SEQ) ? srow[m] : 0.f;
    float v = sv;
    #pragma unroll
    for (int o = 1; o < 32; o <<= 1){
      float n = __shfl_up_sync(0xffffffffu, v, o);
      if (lane >= o) v += n;
    }
    float Pm = run + v, Pp = Pm - sv;
    float w = fminf(Pm, a) - fminf(Pp, a);
    if (m < SEQ){ wb[m] = w; if (pop) srow[m] = sv - w; }
    run += __shfl_sync(0xffffffffu, v, 31);
  }
  __syncwarp();
}

// ------------- token dtype detect -------------
__global__ void k_tok(const void* x){
  __shared__ int ok;
  if (threadIdx.x == 0) ok = 1;
  __syncthreads();
  const long long* xl = (const long long*)x;
  int bad = 0;
  for (int i = threadIdx.x; i < (BN*SEQ)/2; i += 256){
    long long v = xl[i];
    if (v < 0 || v >= 50257) bad = 1;
  }
  if (bad) atomicAnd(&ok, 0);
  __syncthreads();
  if (threadIdx.x == 0) g_is64 = ok;
}

// ------------- prep -------------
__global__ void k_prep(const void* x, const float* emb,
                       const float* wih, const float* whh,
                       const float* bih, const float* bhh,
                       const float* lw, const float* lb,
                       const float* rw, const float* rb,
                       const float* l0w, const float* l1w){
  int gid = blockIdx.x*blockDim.x + threadIdx.x;
  int gsz = gridDim.x*blockDim.x;
  int is64 = g_is64;
  const long long* xl = (const long long*)x;
  const int* xi = (const int*)x;
  for (int i = gid; i < BN*SEQ; i += gsz){
    long long tok = is64 ? xl[i] : (long long)xi[i];
    g_sb[i] = (tok > 0) ? 1.f : 0.f;
  }
  for (int i = gid; i < BN*SEQ*HD; i += gsz){
    int row = i >> 8;
    long long tok = is64 ? xl[row] : (long long)xi[row];
    g_B[i] = emb[(size_t)tok*HD + (i & 255)];
  }
  for (int i = gid; i < 1024*1024; i += gsz){
    int k = i >> 10, j = i & 1023;
    g_Wf[i] = (k < 768) ? wih[j*768 + k] : whh[j*256 + (k-768)];
  }
  for (int i = gid; i < 512*1280; i += gsz){
    int k = i/1280, j = i%1280;
    g_Wt[i] = (k < 256) ? lw[j*256 + k] : rw[j*256 + (k-256)];
  }
  for (int i = gid; i < 1024; i += gsz) g_bf[i] = bih[i] + bhh[i];
  for (int i = gid; i < 1280; i += gsz) g_bt[i] = lb[i] + rb[i];
  for (int i = gid; i < 256*1024; i += gsz){ int k = i >> 10, j = i & 1023; g_Wm0[i] = l0w[j*256 + k]; }
  for (int i = gid; i < 1024*1024; i += gsz){ int k = i >> 10, j = i & 1023; g_Wm1[i] = l1w[j*1024 + k]; }
  for (int i = gid; i < BN*MM*HD; i += gsz) g_V[i] = 0.f;
  for (int i = gid; i < BN*MM; i += gsz) g_s[i] = 0.f;
  for (int i = gid; i < 1024*BN; i += gsz) g_At[i] = 0.f;
  for (int i = gid; i < BN*HD; i += gsz) g_c[i] = 0.f;
}

// ------------- double-buffered f32x2 GEMM -------------
// tile: 64 b x 128 j, k-slice 64 (4 chunks of 16). micro 4b x 8j per thread.
// P[ks][b][j] = sum over slice of At[k][b]*W[k][j]
template<int J, int NKS>
__device__ __forceinline__ void gemm_body2(const float* __restrict__ At,
                                           const float* __restrict__ W,
                                           float* __restrict__ P){
  const int jt = blockIdx.x / NKS, ks = blockIdx.x % NKS;
  const int j0 = jt*128, k0 = ks*64;
  __shared__ float sA[2][16][64];
  __shared__ float sW[2][16][128];
  const int tid = threadIdx.x;
  const int tx = tid & 15, ty = tid >> 4;
  const int aK = tid >> 4, aF = tid & 15;
  const int wK = tid >> 5, wF = tid & 31;
  const float* gA = At + (k0 + aK)*64 + 4*aF;
  const float* gW = W + (size_t)(k0 + wK)*J + j0 + 4*wF;

  float4 ra  = *(const float4*)gA;
  float4 rw0 = *(const float4*)gW;
  float4 rw1 = *(const float4*)(gW + 8*(size_t)J);

  unsigned long long acc[4][4];
  #pragma unroll
  for (int i = 0; i < 4; i++)
    #pragma unroll
    for (int j = 0; j < 4; j++) acc[i][j] = 0ull;

  *(float4*)&sA[0][aK][4*aF]   = ra;
  *(float4*)&sW[0][wK][4*wF]   = rw0;
  *(float4*)&sW[0][wK+8][4*wF] = rw1;
  __syncthreads();

  #pragma unroll 1
  for (int c = 0; c < 4; c++){
    const int p = c & 1;
    if (c < 3){
      ra  = *(const float4*)(gA + (c+1)*16*64);
      rw0 = *(const float4*)(gW + (size_t)((c+1)*16)*J);
      rw1 = *(const float4*)(gW + (size_t)((c+1)*16 + 8)*J);
    }
    #pragma unroll
    for (int kk = 0; kk < 16; kk++){
      float4 a = *(const float4*)&sA[p][kk][4*ty];
      ulonglong2 w0 = *(const ulonglong2*)&sW[p][kk][4*tx];
      ulonglong2 w1 = *(const ulonglong2*)&sW[p][kk][64 + 4*tx];
      unsigned long long a0 = splat2(a.x), a1 = splat2(a.y),
                         a2 = splat2(a.z), a3 = splat2(a.w);
      FMA2(acc[0][0],a0,w0.x); FMA2(acc[0][1],a0,w0.y); FMA2(acc[0][2],a0,w1.x); FMA2(acc[0][3],a0,w1.y);
      FMA2(acc[1][0],a1,w0.x); FMA2(acc[1][1],a1,w0.y); FMA2(acc[1][2],a1,w1.x); FMA2(acc[1][3],a1,w1.y);
      FMA2(acc[2][0],a2,w0.x); FMA2(acc[2][1],a2,w0.y); FMA2(acc[2][2],a2,w1.x); FMA2(acc[2][3],a2,w1.y);
      FMA2(acc[3][0],a3,w0.x); FMA2(acc[3][1],a3,w0.y); FMA2(acc[3][2],a3,w1.x); FMA2(acc[3][3],a3,w1.y);
    }
    if (c < 3){
      __syncthreads();
      *(float4*)&sA[1-p][aK][4*aF]   = ra;
      *(float4*)&sW[1-p][wK][4*wF]   = rw0;
      *(float4*)&sW[1-p][wK+8][4*wF] = rw1;
      __syncthreads();
    }
  }
  #pragma unroll
  for (int i = 0; i < 4; i++){
    int b = 4*ty + i;
    ulonglong2 u0; u0.x = acc[i][0]; u0.y = acc[i][1];
    ulonglong2 u1; u1.x = acc[i][2]; u1.y = acc[i][3];
    *(ulonglong2*)&P[(size_t)(ks*64 + b)*J + j0 + 4*tx]      = u0;
    *(ulonglong2*)&P[(size_t)(ks*64 + b)*J + j0 + 64 + 4*tx] = u1;
  }
}

__global__ void __launch_bounds__(256) k_lstm(){ gemm_body2<1024,16>(g_At,  g_Wf, g_Gp); }
__global__ void __launch_bounds__(256) k_tree(){ gemm_body2<1280, 8>(g_A2t, g_Wt, g_Tp); }

// ------------- pointwise: gates, alphas, popping reads -------------
__global__ void __launch_bounds__(256) k_point(int t, int m0, const float* __restrict__ aw,
                                               const float* __restrict__ ab){
  int b = blockIdx.x, tid = threadIdx.x, warp = tid >> 5, lane = tid & 31;
  __shared__ float sg[1024], w1[224], wt[224], wb[64], red[16];
  __shared__ float s_ar;
  for (int j = tid; j < 1024; j += 256){
    float v = g_bf[j];
    #pragma unroll
    for (int ks = 0; ks < 16; ks++) v += g_Gp[(size_t)(ks*64 + b)*1024 + j];
    sg[j] = v;
  }
  __syncthreads();
  {
    int h = tid;
    float gi = sg[h], gf = sg[256+h], gg = sg[512+h], go = sg[768+h];
    float c = g_c[b*HD + h];
    c = sigf(gf)*c + sigf(gi)*tanhf(gg);
    float hh = sigf(go)*tanhf(c);
    g_c[b*HD + h] = c;
    g_At[(768+h)*64 + b] = hh;
    float p0 = hh*aw[h], p1 = hh*aw[256+h];
    #pragma unroll
    for (int o = 16; o >= 1; o >>= 1){
      p0 += __shfl_xor_sync(0xffffffffu, p0, o);
      p1 += __shfl_xor_sync(0xffffffffu, p1, o);
    }
    if (lane == 0){ red[warp] = p0; red[8+warp] = p1; }
  }
  __syncthreads();
  if (tid == 0){
    float d0 = ab[0], d1 = ab[1];
    for (int w = 0; w < 8; w++){ d0 += red[w]; d1 += red[8+w]; }
    s_ar = sigf(10.f*(d0 - d1));
  }
  __syncthreads();
  float ar = s_ar, as = 1.f - ar;
  int idx = 191 - 2*t, idx2 = 190 - 2*t;
  if (warp == 0){
    scan_stack(&g_s[b*MM], ar, w1, wt, true);
    if (lane == 0){ g_s[b*MM + idx] = ar; g_s[b*MM + idx2] = as; }
  } else if (warp == 1){
    scan_buf(&g_sb[b*SEQ], as, wb, true);
  }
  __syncthreads();
  {
    int h = tid;
    float r1 = 0.f, r2 = 0.f;
    const float* Vb = g_V + (b*MM)*HD + h;
    for (int m = m0; m < MM; m++){
      float tw = wt[m];
      if (tw != 0.f){
        float v = Vb[m*HD];
        r1 = fmaf(w1[m], v, r1);
        r2 = fmaf(tw - w1[m], v, r2);
      }
    }
    g_A2t[h*64 + b] = r1;
    g_A2t[(256+h)*64 + b] = r2;
    float bv = 0.f;
    const float* Bb = g_B + (b*SEQ)*HD + h;
    for (int s2 = 0; s2 < SEQ; s2++){
      float w = wb[s2];
      if (w != 0.f) bv = fmaf(w, Bb[s2*HD], bv);
    }
    g_V[(b*MM + idx2)*HD + h] = bv;
  }
}

// ------------- epilogue: tree cell + next-step alpha=1 reads -------------
__global__ void __launch_bounds__(256) k_epi(int t, int m0){
  int b = blockIdx.x, tid = threadIdx.x, warp = tid >> 5;
  __shared__ float stg[1280], w1[224], wt[224], wb[64];
  if (t >= 0){
    for (int j = tid; j < 1280; j += 256){
      float v = g_bt[j];
      #pragma unroll
      for (int ks = 0; ks < 8; ks++) v += g_Tp[(size_t)(ks*64 + b)*1280 + j];
      stg[j] = v;
    }
    __syncthreads();
    int h = tid;
    float ta = stg[h], ti = stg[256+h], f1 = stg[512+h], f2 = stg[768+h], to = stg[1024+h];
    float r1 = g_A2t[h*64 + b], r2 = g_A2t[(256+h)*64 + b];
    float ct = tanhf(ta)*sigf(ti) + sigf(f1)*r1 + sigf(f2)*r2;
    float ht = sigf(to)*tanhf(ct);
    g_V[(b*MM + (191 - 2*t))*HD + h] = ht;
    __syncthreads();
  }
  if (warp == 0) scan_stack(&g_s[b*MM], 1.f, w1, wt, false);
  else if (warp == 1) scan_buf(&g_sb[b*SEQ], 1.f, wb, false);
  __syncthreads();
  int h = tid;
  float xb = 0.f;
  const float* Bb = g_B + (b*SEQ)*HD + h;
  for (int s2 = 0; s2 < SEQ; s2++){
    float w = wb[s2];
    if (w != 0.f) xb = fmaf(w, Bb[s2*HD], xb);
  }
  float x1 = 0.f, x2 = 0.f;
  const float* Vb = g_V + (b*MM)*HD + h;
  for (int m = m0; m < MM; m++){
    float tw = wt[m];
    if (tw != 0.f){
      float v = Vb[m*HD];
      x1 = fmaf(w1[m], v, x1);
      x2 = fmaf(tw - w1[m], v, x2);
    }
  }
  g_At[h*64 + b] = xb;
  g_At[(256+h)*64 + b] = x1;
  g_At[(512+h)*64 + b] = x2;
}

// ------------- MLP head -------------
__global__ void __launch_bounds__(256) k_mlp0(const float* __restrict__ l0b){
  int b = blockIdx.x, tid = threadIdx.x;
  __shared__ float xs[256];
  xs[tid] = g_At[(256+tid)*64 + b];
  __syncthreads();
  float4 acc = *(const float4*)&l0b[4*tid];
  for (int k = 0; k < 256; k++){
    float4 w = *(const float4*)&g_Wm0[k*1024 + 4*tid];
    float x = xs[k];
    acc.x = fmaf(x, w.x, acc.x); acc.y = fmaf(x, w.y, acc.y);
    acc.z = fmaf(x, w.z, acc.z); acc.w = fmaf(x, w.w, acc.w);
  }
  acc.x = fmaxf(acc.x, 0.f); acc.y = fmaxf(acc.y, 0.f);
  acc.z = fmaxf(acc.z, 0.f); acc.w = fmaxf(acc.w, 0.f);
  *(float4*)&g_y0[b*1024 + 4*tid] = acc;
}

__global__ void __launch_bounds__(256) k_mlp1(const float* __restrict__ l1b){
  int b = blockIdx.x, tid = threadIdx.x;
  __shared__ float xs[1024];
  for (int i = tid; i < 1024; i += 256) xs[i] = g_y0[b*1024 + i];
  __syncthreads();
  float4 acc = *(const float4*)&l1b[4*tid];
  for (int k = 0; k < 1024; k++){
    float4 w = *(const float4*)&g_Wm1[k*1024 + 4*tid];
    float x = xs[k];
    acc.x = fmaf(x, w.x, acc.x); acc.y = fmaf(x, w.y, acc.y);
    acc.z = fmaf(x, w.z, acc.z); acc.w = fmaf(x, w.w, acc.w);
  }
  acc.x = fmaxf(acc.x, 0.f); acc.y = fmaxf(acc.y, 0.f);
  acc.z = fmaxf(acc.z, 0.f); acc.w = fmaxf(acc.w, 0.f);
  *(float4*)&g_y1[b*1024 + 4*tid] = acc;
}

__global__ void __launch_bounds__(256) k_mlp2(const float* __restrict__ l2w,
                                              const float* __restrict__ l2b,
                                              float* __restrict__ out){
  int b = blockIdx.x, tid = threadIdx.x, warp = tid >> 5, lane = tid & 31;
  __shared__ float red[8];
  for (int c = 0; c < 3; c++){
    float p = 0.f;
    for (int k = tid; k < 1024; k += 256)
      p = fmaf(g_y1[b*1024 + k], l2w[c*1024 + k], p);
    #pragma unroll
    for (int o = 16; o >= 1; o >>= 1) p += __shfl_xor_sync(0xffffffffu, p, o);
    if (lane == 0) red[warp] = p;
    __syncthreads();
    if (tid == 0){
      float s = l2b[c];
      for (int w = 0; w < 8; w++) s += red[w];
      out[b*3 + c] = s;
    }
    __syncthreads();
  }
}

// ------------- launch -------------
extern "C" void kernel_launch(void* const* d_in, const int* in_sizes, int n_in,
                              void* d_out, int out_size){
  const void*  x   = d_in[0];
  const float* emb = (const float*)d_in[1];
  const float* wih = (const float*)d_in[2];
  const float* whh = (const float*)d_in[3];
  const float* bih = (const float*)d_in[4];
  const float* bhh = (const float*)d_in[5];
  const float* aw  = (const float*)d_in[6];
  const float* ab  = (const float*)d_in[7];
  const float* lw  = (const float*)d_in[8];
  const float* lb  = (const float*)d_in[9];
  const float* rw  = (const float*)d_in[10];
  const float* rb  = (const float*)d_in[11];
  const float* l0w = (const float*)d_in[12];
  const float* l0b = (const float*)d_in[13];
  const float* l1w = (const float*)d_in[14];
  const float* l1b = (const float*)d_in[15];
  const float* l2w = (const float*)d_in[16];
  const float* l2b = (const float*)d_in[17];
  float* out = (float*)d_out;

  k_tok<<<1, 256>>>(x);
  k_prep<<<512, 256>>>(x, emb, wih, whh, bih, bhh, lw, lb, rw, rb, l0w, l1w);
  {
    int m0 = 192;
    k_epi<<<64, 256>>>(-1, m0);
  }
  for (int t = 0; t < TSTEPS; t++){
    int m0p = 192 - 2*t; if (m0p < 0) m0p = 0;
    int m0e = 190 - 2*t; if (m0e < 0) m0e = 0;
    k_lstm<<<128, 256>>>();
    k_point<<<64, 256>>>(t, m0p, aw, ab);
    k_tree<<<80, 256>>>();
    k_epi<<<64, 256>>>(t, m0e);
  }
  k_mlp0<<<64, 256>>>(l0b);
  k_mlp1<<<64, 256>>>(l1b);
  k_mlp2<<<64, 256>>>(l2w, l2b, out);
}